// round 2
// baseline (speedup 1.0000x reference)
#include <cuda_runtime.h>
#include <math.h>

// ---------------- problem constants ----------------
#define TT     8192          // batch -> time steps
#define CIN    3
#define IH     23
#define IW     30
#define CO     8
#define OH     22
#define OW     29
#define FEAT   5104          // 8*22*29
#define F1     64
#define SS     32            // sensory size
#define NN     19            // LTC units
#define UNF    6
#define KDIM   5104

// ---------------- scratch (static device globals; no allocation) ----------------
__device__ float g_y1 [TT * FEAT];   // conv output, flattened (167 MB)
__device__ float g_fc1[TT * F1];
__device__ float g_seq[TT * SS];
__device__ float g_wns[TT * NN];
__device__ float g_wds[TT * NN];

// LTC precomputed params
__device__ float g_A  [NN * NN];     // sigma * log2(e)            [i][j]
__device__ float g_Bc [NN * NN];     // sigma * mu * log2(e)       [i][j]
__device__ float g_Wp [NN * NN];     // softplus(w) * mask         [i][j]
__device__ float g_We [NN * NN];     // Wp * erev                  [i][j]
__device__ float g_cmt [NN];         // softplus(cm) * UNF
__device__ float g_gvl [NN];         // softplus(gleak) * vleak
__device__ float g_den0[NN];         // cmt + softplus(gleak) + 1e-8

// sensory precomputed params
__device__ float g_sA [SS * NN];
__device__ float g_sB [SS * NN];
__device__ float g_sWp[SS * NN];
__device__ float g_sWe[SS * NN];

// ---------------- helpers ----------------
__device__ __forceinline__ float ex2f(float x) {
    float y; asm("ex2.approx.f32 %0, %1;" : "=f"(y) : "f"(x)); return y;
}
__device__ __forceinline__ float rcpf(float x) {
    float y; asm("rcp.approx.f32 %0, %1;" : "=f"(y) : "f"(x)); return y;
}
__device__ __forceinline__ float softplus_f(float x) {
    // log(1+exp(x)) stable form, matches jax.nn.softplus
    return fmaxf(x, 0.0f) + log1pf(expf(-fabsf(x)));
}

// ---------------- conv (2x2 valid) + ELU + flatten ----------------
__global__ void conv_kernel(const float* __restrict__ x,
                            const float* __restrict__ cw,
                            const float* __restrict__ cb) {
    int idx = blockIdx.x * 256 + threadIdx.x;
    if (idx >= TT * FEAT) return;
    int b   = idx / FEAT;
    int r   = idx - b * FEAT;
    int co  = r / (OH * OW);
    int r2  = r - co * (OH * OW);
    int oh  = r2 / OW;
    int ow_ = r2 - oh * OW;

    const float* xb = x + (size_t)b * (CIN * IH * IW);
    float s = cb[co];
#pragma unroll
    for (int ci = 0; ci < CIN; ci++)
#pragma unroll
        for (int kh = 0; kh < 2; kh++)
#pragma unroll
            for (int kw = 0; kw < 2; kw++)
                s = fmaf(xb[(ci * IH + oh + kh) * IW + ow_ + kw],
                         cw[((co * CIN + ci) * 2 + kh) * 2 + kw], s);
    // ELU (alpha=1), jax uses expm1
    g_y1[idx] = (s > 0.0f) ? s : expm1f(s);
}

// ---------------- param precompute ----------------
__global__ void prep_kernel(const float* __restrict__ sw,  const float* __restrict__ smu,
                            const float* __restrict__ ssig,const float* __restrict__ serev,
                            const float* __restrict__ smask,
                            const float* __restrict__ w,   const float* __restrict__ mu,
                            const float* __restrict__ sigma,const float* __restrict__ erev,
                            const float* __restrict__ mask,
                            const float* __restrict__ gleak,const float* __restrict__ vleak,
                            const float* __restrict__ cm) {
    const float LOG2E = 1.4426950408889634f;
    int i = threadIdx.x;
    if (i < SS * NN) {
        float W = softplus_f(sw[i]) * smask[i];
        g_sWp[i] = W;
        g_sWe[i] = W * serev[i];
        g_sA[i]  = ssig[i] * LOG2E;
        g_sB[i]  = ssig[i] * smu[i] * LOG2E;
    }
    if (i < NN * NN) {
        float W = softplus_f(w[i]) * mask[i];
        g_Wp[i] = W;
        g_We[i] = W * erev[i];
        g_A[i]  = sigma[i] * LOG2E;
        g_Bc[i] = sigma[i] * mu[i] * LOG2E;
    }
    if (i < NN) {
        float c = softplus_f(cm[i]) * (float)UNF;
        float g = softplus_f(gleak[i]);
        g_cmt[i]  = c;
        g_gvl[i]  = g * vleak[i];
        g_den0[i] = c + g + 1e-8f;
    }
}

// ---------------- fc1: (T,5104) x (64,5104)^T + relu ----------------
// BM=64, BN=64(all), BK=16, 256 threads, 4x4 microtile
__global__ void __launch_bounds__(256) fc1_kernel(const float* __restrict__ Wg,
                                                  const float* __restrict__ bg) {
    __shared__ float As[16][68];
    __shared__ float Ws[16][68];
    int tid = threadIdx.x;
    int m0  = blockIdx.x * 64;
    int lr  = tid >> 4;         // 0..15
    int lk  = tid & 15;         // 0..15
    int tx  = tid & 15;         // col group
    int ty  = tid >> 4;         // row group
    float acc[4][4] = {};

    for (int k0 = 0; k0 < KDIM; k0 += 16) {
#pragma unroll
        for (int p = 0; p < 4; p++) {
            int m = lr + 16 * p;
            As[lk][m] = g_y1[(size_t)(m0 + m) * KDIM + k0 + lk];
            Ws[lk][m] = Wg  [(size_t)m        * KDIM + k0 + lk];
        }
        __syncthreads();
#pragma unroll
        for (int kk = 0; kk < 16; kk++) {
            float4 a = *(const float4*)&As[kk][ty * 4];
            float4 b = *(const float4*)&Ws[kk][tx * 4];
            acc[0][0] = fmaf(a.x, b.x, acc[0][0]);
            acc[0][1] = fmaf(a.x, b.y, acc[0][1]);
            acc[0][2] = fmaf(a.x, b.z, acc[0][2]);
            acc[0][3] = fmaf(a.x, b.w, acc[0][3]);
            acc[1][0] = fmaf(a.y, b.x, acc[1][0]);
            acc[1][1] = fmaf(a.y, b.y, acc[1][1]);
            acc[1][2] = fmaf(a.y, b.z, acc[1][2]);
            acc[1][3] = fmaf(a.y, b.w, acc[1][3]);
            acc[2][0] = fmaf(a.z, b.x, acc[2][0]);
            acc[2][1] = fmaf(a.z, b.y, acc[2][1]);
            acc[2][2] = fmaf(a.z, b.z, acc[2][2]);
            acc[2][3] = fmaf(a.z, b.w, acc[2][3]);
            acc[3][0] = fmaf(a.w, b.x, acc[3][0]);
            acc[3][1] = fmaf(a.w, b.y, acc[3][1]);
            acc[3][2] = fmaf(a.w, b.z, acc[3][2]);
            acc[3][3] = fmaf(a.w, b.w, acc[3][3]);
        }
        __syncthreads();
    }
#pragma unroll
    for (int r = 0; r < 4; r++)
#pragma unroll
        for (int c = 0; c < 4; c++) {
            int m = m0 + ty * 4 + r;
            int n = tx * 4 + c;
            float v = acc[r][c] + bg[n];
            g_fc1[m * F1 + n] = fmaxf(v, 0.0f);
        }
}

// ---------------- fc2 + input mapping -> seq ----------------
__global__ void fc2_kernel(const float* __restrict__ W2, const float* __restrict__ b2,
                           const float* __restrict__ iw, const float* __restrict__ ib) {
    __shared__ float Wsh[F1 * SS];   // transposed: Wsh[k*32+n]
    int tid = threadIdx.x;
    for (int q = tid; q < SS * F1; q += 256) {
        int n = q / F1, k = q - n * F1;
        Wsh[k * SS + n] = W2[q];
    }
    __syncthreads();
    int idx = blockIdx.x * 256 + tid;
    int t = idx >> 5, n = idx & 31;
    const float* row = g_fc1 + t * F1;
    float acc = b2[n];
#pragma unroll
    for (int k = 0; k < F1; k++)
        acc = fmaf(row[k], Wsh[k * SS + n], acc);
    g_seq[idx] = fmaf(acc, iw[n], ib[n]);
}

// ---------------- sensory synapse precompute ----------------
__global__ void sensory_kernel() {
    int idx = blockIdx.x * 256 + threadIdx.x;
    int t = idx >> 5, j = idx & 31;
    if (j >= NN) return;
    const float* sq = g_seq + t * SS;
    float accN = 0.0f, accD = 0.0f;
#pragma unroll
    for (int i = 0; i < SS; i++) {
        float s = sq[i];
        float e = exp2f(g_sB[i * NN + j] - g_sA[i * NN + j] * s);
        float gate = 1.0f / (1.0f + e);
        accN = fmaf(g_sWe[i * NN + j], gate, accN);
        accD = fmaf(g_sWp[i * NN + j], gate, accD);
    }
    g_wns[t * NN + j] = accN;
    g_wds[t * NN + j] = accD;
}

// ---------------- LTC sequential scan: 1 warp, lane = target neuron ----------------
__global__ void __launch_bounds__(32, 1) ltc_kernel(const float* __restrict__ ow,
                                                    const float* __restrict__ ob,
                                                    float* __restrict__ out) {
    int j  = threadIdx.x;
    int jj = (j < NN) ? j : 0;

    float A[NN], Bc[NN], Wp[NN], We[NN];
#pragma unroll
    for (int i = 0; i < NN; i++) {
        A[i]  = g_A [i * NN + jj];
        Bc[i] = g_Bc[i * NN + jj];
        Wp[i] = g_Wp[i * NN + jj];
        We[i] = g_We[i * NN + jj];
    }
    float cmt   = g_cmt [jj];
    float basen = g_gvl [jj];
    float based = g_den0[jj];
    float owv = ow[0], obv = ob[0];

    float v = 0.0f;
    float wns_c = g_wns[jj];
    float wds_c = g_wds[jj];

    for (int t = 0; t < TT; t++) {
        int tn = (t + 1 < TT) ? (t + 1) : t;
        float wns_n = g_wns[tn * NN + jj];   // prefetch next step
        float wds_n = g_wds[tn * NN + jj];

#pragma unroll 2
        for (int u = 0; u < UNF; u++) {
            float accN[4], accD[4];
            accN[0] = basen + wns_c; accN[1] = 0.0f; accN[2] = 0.0f; accN[3] = 0.0f;
            accD[0] = based + wds_c; accD[1] = 0.0f; accD[2] = 0.0f; accD[3] = 0.0f;
#pragma unroll
            for (int i = 0; i < NN; i++) {
                float vi = __shfl_sync(0xffffffffu, v, i);
                float e  = ex2f(fmaf(-A[i], vi, Bc[i]));   // 2^(B - A*v) = exp(-sigma*(v-mu))
                float s  = rcpf(1.0f + e);                 // sigmoid
                accN[i & 3] = fmaf(We[i], s, accN[i & 3]);
                accD[i & 3] = fmaf(Wp[i], s, accD[i & 3]);
            }
            float wn = (accN[0] + accN[1]) + (accN[2] + accN[3]);
            float wd = (accD[0] + accD[1]) + (accD[2] + accD[3]);
            v = fmaf(cmt, v, wn) * rcpf(wd);
        }
        if (j == 0) out[t] = fmaf(v, owv, obv);
        wns_c = wns_n;
        wds_c = wds_n;
    }
}

// ---------------- launcher ----------------
extern "C" void kernel_launch(void* const* d_in, const int* in_sizes, int n_in,
                              void* d_out, int out_size) {
    const float* x       = (const float*)d_in[0];
    const float* conv_w  = (const float*)d_in[1];
    const float* conv_b  = (const float*)d_in[2];
    const float* fc1_w   = (const float*)d_in[3];
    const float* fc1_b   = (const float*)d_in[4];
    const float* fc2_w   = (const float*)d_in[5];
    const float* fc2_b   = (const float*)d_in[6];
    const float* input_w = (const float*)d_in[7];
    const float* input_b = (const float*)d_in[8];
    const float* s_w     = (const float*)d_in[9];
    const float* s_mu    = (const float*)d_in[10];
    const float* s_sig   = (const float*)d_in[11];
    const float* s_erev  = (const float*)d_in[12];
    const float* s_mask  = (const float*)d_in[13];
    const float* w_      = (const float*)d_in[14];
    const float* mu_     = (const float*)d_in[15];
    const float* sigma_  = (const float*)d_in[16];
    const float* erev_   = (const float*)d_in[17];
    const float* mask_   = (const float*)d_in[18];
    const float* gleak   = (const float*)d_in[19];
    const float* vleak   = (const float*)d_in[20];
    const float* cm      = (const float*)d_in[21];
    const float* out_w   = (const float*)d_in[22];
    const float* out_b   = (const float*)d_in[23];
    float* out = (float*)d_out;

    conv_kernel<<<(TT * FEAT + 255) / 256, 256>>>(x, conv_w, conv_b);
    prep_kernel<<<1, 1024>>>(s_w, s_mu, s_sig, s_erev, s_mask,
                             w_, mu_, sigma_, erev_, mask_,
                             gleak, vleak, cm);
    fc1_kernel<<<TT / 64, 256>>>(fc1_w, fc1_b);
    fc2_kernel<<<(TT * SS) / 256, 256>>>(fc2_w, fc2_b, input_w, input_b);
    sensory_kernel<<<(TT * 32) / 256, 256>>>();
    ltc_kernel<<<1, 32>>>(out_w, out_b, out);
}